// round 14
// baseline (speedup 1.0000x reference)
#include <cuda_runtime.h>
#include <cuda_fp16.h>

#define Nn 100000
#define Ee 1600000
#define Dd 128
#define Hh 256
#define Ll 40
#define NB 98   // ceil(Nn / 1024)

// ---------------- scratch ------------------------------------------------------
__device__ int   g_degi[Nn];
__device__ int   g_offs[Nn + 1];
__device__ int   g_col[Ee];
__device__ int   g_part[NB];
__device__ float g_dinv[Nn];
__device__ __half g_xh[(size_t)Nn * Dd];      // prescaled fp16 features / h3
__device__ __half g_aggH[(size_t)Nn * Dd];    // fp16 gather output
__device__ __half g_hidH[(size_t)Nn * Hh];    // fp16 MLP hidden
// transposed fp16 hi/lo weights [N][K], packed:
//   W0,W1,W2: 128x128 ; Wm1: 256x128 ; Wm2: 64(pad from 40)x256
#define WT0 0
#define WT1 16384
#define WT2 32768
#define WTM1 49152
#define WTM2 81920
#define WTOT 98304
__device__ __half g_wtH[WTOT];
__device__ __half g_wtL[WTOT];

// ---------------- CSR build ----------------------------------------------------
__global__ void k_zero(int* __restrict__ a, int n) {
    int i = blockIdx.x * blockDim.x + threadIdx.x;
    if (i < n) a[i] = 0;
}

__global__ void k_count(const int* __restrict__ ei, int* __restrict__ degi, int e) {
    int i = blockIdx.x * blockDim.x + threadIdx.x;
    if (i < e) atomicAdd(&degi[ei[i]], 1);
}

// block partial sums + dinv (fused)
__global__ void k_scanA(const int* __restrict__ degi, int* __restrict__ part,
                        float* __restrict__ dinv) {
    __shared__ int s[1024];
    int i = blockIdx.x * 1024 + threadIdx.x;
    int v = (i < Nn) ? degi[i] : 0;
    if (i < Nn) dinv[i] = rsqrtf((float)v + 1.0f);
    s[threadIdx.x] = v;
    __syncthreads();
    for (int d = 512; d > 0; d >>= 1) {
        if (threadIdx.x < d) s[threadIdx.x] += s[threadIdx.x + d];
        __syncthreads();
    }
    if (threadIdx.x == 0) part[blockIdx.x] = s[0];
}

// per-block exclusive scan; base computed in-block from partials (fused scanB)
__global__ void k_scanC(const int* __restrict__ degi, const int* __restrict__ part,
                        int* __restrict__ offs) {
    __shared__ int sp[128];
    __shared__ int s[1024];
    int t = threadIdx.x;
    if (t < 128) sp[t] = (t < NB) ? part[t] : 0;
    __syncthreads();
    for (int d = 1; d < 128; d <<= 1) {
        int u = 0;
        if (t < 128 && t >= d) u = sp[t - d];
        __syncthreads();
        if (t < 128) sp[t] += u;
        __syncthreads();
    }
    int base = (blockIdx.x == 0) ? 0 : sp[blockIdx.x - 1];
    int i = blockIdx.x * 1024 + t;
    int v = (i < Nn) ? degi[i] : 0;
    s[t] = v;
    __syncthreads();
    for (int d = 1; d < 1024; d <<= 1) {
        int u = (t >= d) ? s[t - d] : 0;
        __syncthreads();
        s[t] += u;
        __syncthreads();
    }
    int exc = s[t] - v + base;
    if (i < Nn) {
        offs[i] = exc;
        if (i == Nn - 1) offs[Nn] = exc + v;
    }
}

__global__ void k_fill(const int* __restrict__ ei, const int* __restrict__ offs,
                       int* __restrict__ degi, int* __restrict__ col, int e) {
    int i = blockIdx.x * blockDim.x + threadIdx.x;
    if (i < e) {
        int r = ei[i];
        int c = ei[e + i];
        int pos = offs[r] + atomicSub(&degi[r], 1) - 1;
        col[pos] = c;
    }
}

// ---------------- fused weight conversion: all 5 weights -> fp16 hi/lo --------
__global__ void k_wconv_all(const float* __restrict__ W0, const float* __restrict__ W1,
                            const float* __restrict__ W2, const float* __restrict__ Wm1,
                            const float* __restrict__ Wm2,
                            __half* __restrict__ H, __half* __restrict__ L) {
    int i = blockIdx.x * blockDim.x + threadIdx.x;
    if (i >= WTOT) return;
    float w;
    if (i < WTM1) {                       // W0/W1/W2: dest [n][k], K=128, N=128
        const float* W = (i < WT1) ? W0 : (i < WT2) ? W1 : W2;
        int j = i & 16383;
        int n = j >> 7, k = j & 127;
        w = W[k * 128 + n];
    } else if (i < WTM2) {                // Wm1: dest [n][k], n<256, K=128
        int j = i - WTM1;
        int n = j >> 7, k = j & 127;
        w = Wm1[k * 256 + n];
    } else {                              // Wm2: dest [n][k], n<64 (pad 40), K=256
        int j = i - WTM2;
        int n = j >> 8, k = j & 255;
        w = (n < Ll) ? Wm2[k * Ll + n] : 0.f;
    }
    __half h = __float2half_rn(w);
    __half l = __float2half_rn(w - __half2float(h));
    H[i] = h;
    L[i] = l;
}

// ---------------- fp32 -> prescaled fp16: xh = fp16(dinv[row] * x) ------------
__global__ void k_f2h(const float4* __restrict__ x, const float* __restrict__ dinv,
                      uint2* __restrict__ xh, int n4) {
    int t = blockIdx.x * blockDim.x + threadIdx.x;
    if (t < n4) {
        float d = __ldg(&dinv[t >> 5]);
        float4 v = x[t];
        __half2 a = __floats2half2_rn(v.x * d, v.y * d);
        __half2 b = __floats2half2_rn(v.z * d, v.w * d);
        uint2 u;
        u.x = *(unsigned*)&a;
        u.y = *(unsigned*)&b;
        xh[t] = u;
    }
}

// ---------------- aggregation: warp/node, prescaled fp16, pure sum ------------
__device__ __forceinline__ float4 h4_to_f4(uint2 u) {
    float2 f0 = __half22float2(*reinterpret_cast<__half2*>(&u.x));
    float2 f1 = __half22float2(*reinterpret_cast<__half2*>(&u.y));
    return make_float4(f0.x, f0.y, f1.x, f1.y);
}

__global__ void k_gather_h(const int* __restrict__ offs, const int* __restrict__ col,
                           const float* __restrict__ dinv, const uint2* __restrict__ src,
                           uint2* __restrict__ dst) {
    int w    = (int)((blockIdx.x * (size_t)blockDim.x + threadIdx.x) >> 5);
    int lane = threadIdx.x & 31;
    if (w >= Nn) return;

    float4 acc = h4_to_f4(__ldg(&src[(size_t)w * 32 + lane]));   // self term

    int beg = __ldg(&offs[w]), end = __ldg(&offs[w + 1]);
    int c = (beg < end) ? __ldg(&col[beg]) : 0;
    for (int j = beg; j < end; j++) {
        int cn = (j + 1 < end) ? __ldg(&col[j + 1]) : 0;   // prefetch next index
        float4 v = h4_to_f4(__ldg(&src[(size_t)c * 32 + lane]));
        acc.x += v.x; acc.y += v.y; acc.z += v.z; acc.w += v.w;
        c = cn;
    }
    float di = __ldg(&dinv[w]);
    __half2 p0 = __floats2half2_rn(acc.x * di, acc.y * di);
    __half2 p1 = __floats2half2_rn(acc.z * di, acc.w * di);
    uint2 u;
    u.x = *(unsigned*)&p0;
    u.y = *(unsigned*)&p1;
    dst[(size_t)w * 32 + lane] = u;
}

// ---------------- fp16 2-MMA split tensor-core GEMM (persistent CTAs) ---------
__device__ __forceinline__ void mma16816h(float* c, const unsigned* a, unsigned b0, unsigned b1) {
    asm volatile(
        "mma.sync.aligned.m16n8k16.row.col.f32.f16.f16.f32 "
        "{%0,%1,%2,%3},{%4,%5,%6,%7},{%8,%9},{%0,%1,%2,%3};"
        : "+f"(c[0]), "+f"(c[1]), "+f"(c[2]), "+f"(c[3])
        : "r"(a[0]), "r"(a[1]), "r"(a[2]), "r"(a[3]), "r"(b0), "r"(b1));
}

// W staged ONCE per CTA; loop over M tiles with stride gridDim.x.
// OUTH: write fp16; PRESCALE: multiply rows by dinv before store (requires OUTH).
template<int KEL, int NTILE, int NVALID, bool RELU, bool OUTH, bool PRESCALE>
__global__ void k_gemm_tc(const __half* __restrict__ Ah, const __half* __restrict__ WtH,
                          const __half* __restrict__ WtL, const float* __restrict__ bias,
                          const float* __restrict__ dinv, void* __restrict__ outv,
                          int nrows, int ldc) {
    constexpr int KSTR  = KEL + 8;
    constexpr int NT    = NTILE / 2;   // warp n-extent
    constexpr int NFRAG = NT / 8;
    extern __shared__ __half smb[];
    __half* As  = smb;                     // 128 x KSTR
    __half* WsH = As + 128 * KSTR;         // NTILE x KSTR
    __half* WsL = WsH + NTILE * KSTR;      // NTILE x KSTR

    int tid = threadIdx.x;
    int n0 = blockIdx.y * NTILE;

    constexpr int C8 = KEL / 8;   // uint4 chunks per row (8 halfs each)
    // stage Wt slice (rows n0..n0+NTILE-1), ONCE
    {
        const uint4* GH = (const uint4*)(WtH + (size_t)n0 * KEL);
        const uint4* GL = (const uint4*)(WtL + (size_t)n0 * KEL);
#pragma unroll
        for (int it = 0; it < NTILE * C8 / 256; it++) {
            int i = tid + 256 * it;
            int r = i / C8, c = i % C8;
            *(uint4*)((char*)WsH + r * (KSTR * 2) + c * 16) = GH[r * C8 + c];
            *(uint4*)((char*)WsL + r * (KSTR * 2) + c * 16) = GL[r * C8 + c];
        }
    }

    int lane = tid & 31, wid = tid >> 5;
    int wm = (wid & 3) * 32;
    int wn = (wid >> 2) * NT;
    int g = lane >> 2, t = lane & 3;

    // hoist bias (and column validity) out of the M loop
    float bv[NFRAG][2];
    bool  cokv[NFRAG];
#pragma unroll
    for (int nt = 0; nt < NFRAG; nt++) {
        int cg = n0 + wn + nt * 8 + 2 * t;
        cokv[nt] = cg < NVALID;
        bv[nt][0] = cokv[nt] ? bias[cg] : 0.f;
        bv[nt][1] = cokv[nt] ? bias[cg + 1] : 0.f;
    }

    int tiles = (nrows + 127) >> 7;
    for (int mb = blockIdx.x; mb < tiles; mb += gridDim.x) {
        int m0 = mb << 7;

        // stage A tile: raw fp16 copy, 16B chunks
        {
            const uint4* GA = (const uint4*)Ah;
#pragma unroll
            for (int it = 0; it < 128 * C8 / 256; it++) {
                int i = tid + 256 * it;
                int r = i / C8, c = i % C8;
                uint4 v = (m0 + r < nrows) ? __ldg(&GA[(size_t)(m0 + r) * C8 + c])
                                           : make_uint4(0u, 0u, 0u, 0u);
                *(uint4*)&As[r * KSTR + c * 8] = v;
            }
        }
        __syncthreads();

        float acc[2][NFRAG][4];
#pragma unroll
        for (int mt = 0; mt < 2; mt++)
#pragma unroll
            for (int nt = 0; nt < NFRAG; nt++)
#pragma unroll
                for (int q = 0; q < 4; q++) acc[mt][nt][q] = 0.f;

#pragma unroll
        for (int ks = 0; ks < KEL / 16; ks++) {
            int k0 = ks * 16;
            unsigned aF[2][4];
#pragma unroll
            for (int mt = 0; mt < 2; mt++) {
                int r = wm + mt * 16;
                aF[mt][0] = *(const unsigned*)&As[(r + g) * KSTR + k0 + 2 * t];
                aF[mt][1] = *(const unsigned*)&As[(r + g + 8) * KSTR + k0 + 2 * t];
                aF[mt][2] = *(const unsigned*)&As[(r + g) * KSTR + k0 + 8 + 2 * t];
                aF[mt][3] = *(const unsigned*)&As[(r + g + 8) * KSTR + k0 + 8 + 2 * t];
            }
#pragma unroll
            for (int nt = 0; nt < NFRAG; nt++) {
                int nn = wn + nt * 8 + g;
                unsigned bH0 = *(const unsigned*)&WsH[nn * KSTR + k0 + 2 * t];
                unsigned bH1 = *(const unsigned*)&WsH[nn * KSTR + k0 + 8 + 2 * t];
                unsigned bL0 = *(const unsigned*)&WsL[nn * KSTR + k0 + 2 * t];
                unsigned bL1 = *(const unsigned*)&WsL[nn * KSTR + k0 + 8 + 2 * t];
#pragma unroll
                for (int mt = 0; mt < 2; mt++) {
                    mma16816h(acc[mt][nt], aF[mt], bH0, bH1);
                    mma16816h(acc[mt][nt], aF[mt], bL0, bL1);
                }
            }
        }

        // epilogue
#pragma unroll
        for (int nt = 0; nt < NFRAG; nt++) {
            int cg = n0 + wn + nt * 8 + 2 * t;
            bool cok = cokv[nt];
            float bv0 = bv[nt][0], bv1 = bv[nt][1];
#pragma unroll
            for (int mt = 0; mt < 2; mt++) {
                int r0 = m0 + wm + mt * 16 + g;
                float v0 = acc[mt][nt][0] + bv0, v1 = acc[mt][nt][1] + bv1;
                float v2 = acc[mt][nt][2] + bv0, v3 = acc[mt][nt][3] + bv1;
                if (RELU) {
                    v0 = fmaxf(v0, 0.f); v1 = fmaxf(v1, 0.f);
                    v2 = fmaxf(v2, 0.f); v3 = fmaxf(v3, 0.f);
                }
                if (OUTH) {
                    float d0 = 1.f, d1 = 1.f;
                    if (PRESCALE) {
                        d0 = (r0 < nrows) ? __ldg(&dinv[r0]) : 0.f;
                        d1 = (r0 + 8 < nrows) ? __ldg(&dinv[r0 + 8]) : 0.f;
                    }
                    __half* oh = (__half*)outv;
                    if (cok && r0 < nrows)
                        *(__half2*)&oh[(size_t)r0 * ldc + cg] = __floats2half2_rn(v0 * d0, v1 * d0);
                    if (cok && r0 + 8 < nrows)
                        *(__half2*)&oh[(size_t)(r0 + 8) * ldc + cg] = __floats2half2_rn(v2 * d1, v3 * d1);
                } else {
                    float* of = (float*)outv;
                    if (cok && r0 < nrows) {
                        of[(size_t)r0 * ldc + cg]     = v0;
                        of[(size_t)r0 * ldc + cg + 1] = v1;
                    }
                    if (cok && r0 + 8 < nrows) {
                        of[(size_t)(r0 + 8) * ldc + cg]     = v2;
                        of[(size_t)(r0 + 8) * ldc + cg + 1] = v3;
                    }
                }
            }
        }
        __syncthreads();   // protect As before next iteration restages
    }
}

#define SMEM_TC  (3 * 128 * 136 * 2)               // 104448 (KEL=128, NTILE=128)
#define SMEM_M2  ((128 + 2 * 64) * 264 * 2)        // 135168 (KEL=256, NTILE=64)

extern "C" void kernel_launch(void* const* d_in, const int* in_sizes, int n_in,
                              void* d_out, int out_size) {
    const float* x   = (const float*)d_in[0];
    const int*   ei  = (const int*)  d_in[1];
    const float* W0  = (const float*)d_in[2];
    const float* b0  = (const float*)d_in[3];
    const float* W1  = (const float*)d_in[4];
    const float* b1  = (const float*)d_in[5];
    const float* W2  = (const float*)d_in[6];
    const float* b2  = (const float*)d_in[7];
    const float* Wm1 = (const float*)d_in[8];
    const float* bm1 = (const float*)d_in[9];
    const float* Wm2 = (const float*)d_in[10];
    const float* bm2 = (const float*)d_in[11];
    float* out = (float*)d_out;

    const int n = Nn, e = Ee;

    int *degi, *offs, *col, *part;
    float *dinv;
    __half *xh, *aggH, *hidH, *wtH, *wtL;
    cudaGetSymbolAddress((void**)&degi, g_degi);
    cudaGetSymbolAddress((void**)&offs, g_offs);
    cudaGetSymbolAddress((void**)&col,  g_col);
    cudaGetSymbolAddress((void**)&part, g_part);
    cudaGetSymbolAddress((void**)&dinv, g_dinv);
    cudaGetSymbolAddress((void**)&xh,   g_xh);
    cudaGetSymbolAddress((void**)&aggH, g_aggH);
    cudaGetSymbolAddress((void**)&hidH, g_hidH);
    cudaGetSymbolAddress((void**)&wtH,  g_wtH);
    cudaGetSymbolAddress((void**)&wtL,  g_wtL);

    cudaFuncSetAttribute(k_gemm_tc<128, 128, 128, true, true, true>,
                         cudaFuncAttributeMaxDynamicSharedMemorySize, SMEM_TC);
    cudaFuncSetAttribute(k_gemm_tc<128, 128, 128, true, true, false>,
                         cudaFuncAttributeMaxDynamicSharedMemorySize, SMEM_TC);
    cudaFuncSetAttribute(k_gemm_tc<128, 128, 256, true, true, false>,
                         cudaFuncAttributeMaxDynamicSharedMemorySize, SMEM_TC);
    cudaFuncSetAttribute(k_gemm_tc<256, 64, 40, false, false, false>,
                         cudaFuncAttributeMaxDynamicSharedMemorySize, SMEM_M2);

    const int TB = 256;
    dim3 gN((n + TB - 1) / TB);
    dim3 gE((e + TB - 1) / TB);
    dim3 gNW(((size_t)n * 32 + TB - 1) / TB);
    dim3 gF2H(((size_t)n * 32 + TB - 1) / TB);
    dim3 gP(296, 1);     // persistent: 2 CTAs/SM (104.4 KB smem)
    dim3 gP2(148, 2);    // MLP1: 2 CTAs/SM, one per N half
    dim3 gP1(148, 1);    // MLP2: 1 CTA/SM (135 KB smem)

    // ---- CSR build + normalization (5 launches) ----
    k_zero <<<gN, TB>>>(degi, n);
    k_count<<<gE, TB>>>(ei, degi, e);
    k_scanA<<<NB, 1024>>>(degi, part, dinv);
    k_scanC<<<NB, 1024>>>(degi, part, offs);
    k_fill <<<gE, TB>>>(ei, offs, degi, col, e);

    // ---- fused weight conversion (1 launch) ----
    k_wconv_all<<<(WTOT + 255) / 256, 256>>>(W0, W1, W2, Wm1, Wm2, wtH, wtL);

    // ---- x -> prescaled fp16 ----
    k_f2h<<<gF2H, TB>>>((const float4*)x, dinv, (uint2*)xh, n * 32);

    // ---- layer 0: gather -> fp16 agg, GEMM -> prescaled fp16 h1 (in xh) ----
    k_gather_h<<<gNW, TB>>>(offs, col, dinv, (const uint2*)xh, (uint2*)aggH);
    k_gemm_tc<128, 128, 128, true, true, true><<<gP, TB, SMEM_TC>>>(
        aggH, wtH + WT0, wtL + WT0, b0, dinv, xh, n, 128);

    // ---- layer 1 ----
    k_gather_h<<<gNW, TB>>>(offs, col, dinv, (const uint2*)xh, (uint2*)aggH);
    k_gemm_tc<128, 128, 128, true, true, true><<<gP, TB, SMEM_TC>>>(
        aggH, wtH + WT1, wtL + WT1, b1, dinv, xh, n, 128);

    // ---- layer 2: gather, GEMM -> plain fp16 h3 (in xh) ----
    k_gather_h<<<gNW, TB>>>(offs, col, dinv, (const uint2*)xh, (uint2*)aggH);
    k_gemm_tc<128, 128, 128, true, true, false><<<gP, TB, SMEM_TC>>>(
        aggH, wtH + WT2, wtL + WT2, b2, dinv, xh, n, 128);

    // ---- MLP: h3(fp16) -> hid(fp16) -> out(fp32) ----
    k_gemm_tc<128, 128, 256, true, true, false><<<gP2, TB, SMEM_TC>>>(
        xh, wtH + WTM1, wtL + WTM1, bm1, dinv, hidH, n, 256);
    k_gemm_tc<256, 64, 40, false, false, false><<<gP1, TB, SMEM_M2>>>(
        hidH, wtH + WTM2, wtL + WTM2, bm2, dinv, out, n, 40);
}

// round 15
// speedup vs baseline: 1.0123x; 1.0123x over previous
#include <cuda_runtime.h>
#include <cuda_fp16.h>

#define Nn 100000
#define Ee 1600000
#define Dd 128
#define Hh 256
#define Ll 40
#define NB 98   // ceil(Nn / 1024)

// ---------------- scratch ------------------------------------------------------
__device__ int   g_degi[Nn];
__device__ int   g_offs[Nn + 1];
__device__ int   g_col[Ee];
__device__ int   g_part[NB];
__device__ float g_dinv[Nn];
__device__ __half g_xh[(size_t)Nn * Dd];      // prescaled fp16 features / h3
__device__ __half g_aggH[(size_t)Nn * Dd];    // fp16 gather output
__device__ __half g_hidH[(size_t)Nn * Hh];    // fp16 MLP hidden
// transposed fp16 hi/lo weights [N][K], packed:
//   W0,W1,W2: 128x128 ; Wm1: 256x128 ; Wm2: 64(pad from 40)x256
#define WT0 0
#define WT1 16384
#define WT2 32768
#define WTM1 49152
#define WTM2 81920
#define WTOT 98304
__device__ __half g_wtH[WTOT];
__device__ __half g_wtL[WTOT];

// ---------------- CSR build ----------------------------------------------------
__global__ void k_zero(int* __restrict__ a, int n) {
    int i = blockIdx.x * blockDim.x + threadIdx.x;
    if (i < n) a[i] = 0;
}

__global__ void k_count(const int* __restrict__ ei, int* __restrict__ degi, int e) {
    int i = blockIdx.x * blockDim.x + threadIdx.x;
    if (i < e) atomicAdd(&degi[ei[i]], 1);
}

// block partial sums + dinv (fused)
__global__ void k_scanA(const int* __restrict__ degi, int* __restrict__ part,
                        float* __restrict__ dinv) {
    __shared__ int s[1024];
    int i = blockIdx.x * 1024 + threadIdx.x;
    int v = (i < Nn) ? degi[i] : 0;
    if (i < Nn) dinv[i] = rsqrtf((float)v + 1.0f);
    s[threadIdx.x] = v;
    __syncthreads();
    for (int d = 512; d > 0; d >>= 1) {
        if (threadIdx.x < d) s[threadIdx.x] += s[threadIdx.x + d];
        __syncthreads();
    }
    if (threadIdx.x == 0) part[blockIdx.x] = s[0];
}

// per-block exclusive scan; base computed in-block from partials (fused scanB)
__global__ void k_scanC(const int* __restrict__ degi, const int* __restrict__ part,
                        int* __restrict__ offs) {
    __shared__ int sp[128];
    __shared__ int s[1024];
    int t = threadIdx.x;
    if (t < 128) sp[t] = (t < NB) ? part[t] : 0;
    __syncthreads();
    for (int d = 1; d < 128; d <<= 1) {
        int u = 0;
        if (t < 128 && t >= d) u = sp[t - d];
        __syncthreads();
        if (t < 128) sp[t] += u;
        __syncthreads();
    }
    int base = (blockIdx.x == 0) ? 0 : sp[blockIdx.x - 1];
    int i = blockIdx.x * 1024 + t;
    int v = (i < Nn) ? degi[i] : 0;
    s[t] = v;
    __syncthreads();
    for (int d = 1; d < 1024; d <<= 1) {
        int u = (t >= d) ? s[t - d] : 0;
        __syncthreads();
        s[t] += u;
        __syncthreads();
    }
    int exc = s[t] - v + base;
    if (i < Nn) {
        offs[i] = exc;
        if (i == Nn - 1) offs[Nn] = exc + v;
    }
}

__global__ void k_fill(const int* __restrict__ ei, const int* __restrict__ offs,
                       int* __restrict__ degi, int* __restrict__ col, int e) {
    int i = blockIdx.x * blockDim.x + threadIdx.x;
    if (i < e) {
        int r = ei[i];
        int c = ei[e + i];
        int pos = offs[r] + atomicSub(&degi[r], 1) - 1;
        col[pos] = c;
    }
}

// ---------------- fused weight conversion: all 5 weights -> fp16 hi/lo --------
__global__ void k_wconv_all(const float* __restrict__ W0, const float* __restrict__ W1,
                            const float* __restrict__ W2, const float* __restrict__ Wm1,
                            const float* __restrict__ Wm2,
                            __half* __restrict__ H, __half* __restrict__ L) {
    int i = blockIdx.x * blockDim.x + threadIdx.x;
    if (i >= WTOT) return;
    float w;
    if (i < WTM1) {                       // W0/W1/W2: dest [n][k], K=128, N=128
        const float* W = (i < WT1) ? W0 : (i < WT2) ? W1 : W2;
        int j = i & 16383;
        int n = j >> 7, k = j & 127;
        w = W[k * 128 + n];
    } else if (i < WTM2) {                // Wm1: dest [n][k], n<256, K=128
        int j = i - WTM1;
        int n = j >> 7, k = j & 127;
        w = Wm1[k * 256 + n];
    } else {                              // Wm2: dest [n][k], n<64 (pad 40), K=256
        int j = i - WTM2;
        int n = j >> 8, k = j & 255;
        w = (n < Ll) ? Wm2[k * Ll + n] : 0.f;
    }
    __half h = __float2half_rn(w);
    __half l = __float2half_rn(w - __half2float(h));
    H[i] = h;
    L[i] = l;
}

// ---------------- fp32 -> prescaled fp16: xh = fp16(dinv[row] * x) ------------
__global__ void k_f2h(const float4* __restrict__ x, const float* __restrict__ dinv,
                      uint2* __restrict__ xh, int n4) {
    int t = blockIdx.x * blockDim.x + threadIdx.x;
    if (t < n4) {
        float d = __ldg(&dinv[t >> 5]);
        float4 v = x[t];
        __half2 a = __floats2half2_rn(v.x * d, v.y * d);
        __half2 b = __floats2half2_rn(v.z * d, v.w * d);
        uint2 u;
        u.x = *(unsigned*)&a;
        u.y = *(unsigned*)&b;
        xh[t] = u;
    }
}

// ---------------- aggregation: 2 nodes per warp, 16 lanes each, uint4 ---------
// src[c] = fp16(dinv[c]*h[c]);  dst[r] = fp16( dinv[r] * (src[r] + sum src[c]) )
__global__ void k_gather_h(const int* __restrict__ offs, const int* __restrict__ col,
                           const float* __restrict__ dinv, const uint4* __restrict__ src,
                           uint4* __restrict__ dst) {
    int gw   = (int)((blockIdx.x * (size_t)blockDim.x + threadIdx.x) >> 5);
    int lane = threadIdx.x & 31;
    int node = gw * 2 + (lane >> 4);   // two nodes per warp
    int l16  = lane & 15;              // 16 lanes x uint4(8 halfs) = 128 features
    if (node >= Nn) return;

    // self term
    uint4 u = __ldg(&src[(size_t)node * 16 + l16]);
    float2 f0 = __half22float2(*(__half2*)&u.x);
    float2 f1 = __half22float2(*(__half2*)&u.y);
    float2 f2 = __half22float2(*(__half2*)&u.z);
    float2 f3 = __half22float2(*(__half2*)&u.w);
    float a0 = f0.x, a1 = f0.y, a2 = f1.x, a3 = f1.y;
    float a4 = f2.x, a5 = f2.y, a6 = f3.x, a7 = f3.y;

    int beg = __ldg(&offs[node]), end = __ldg(&offs[node + 1]);
    int c = (beg < end) ? __ldg(&col[beg]) : 0;
    for (int j = beg; j < end; j++) {
        int cn = (j + 1 < end) ? __ldg(&col[j + 1]) : 0;   // prefetch next index
        uint4 v = __ldg(&src[(size_t)c * 16 + l16]);
        float2 g0 = __half22float2(*(__half2*)&v.x);
        float2 g1 = __half22float2(*(__half2*)&v.y);
        float2 g2 = __half22float2(*(__half2*)&v.z);
        float2 g3 = __half22float2(*(__half2*)&v.w);
        a0 += g0.x; a1 += g0.y; a2 += g1.x; a3 += g1.y;
        a4 += g2.x; a5 += g2.y; a6 += g3.x; a7 += g3.y;
        c = cn;
    }
    float di = __ldg(&dinv[node]);
    __half2 p0 = __floats2half2_rn(a0 * di, a1 * di);
    __half2 p1 = __floats2half2_rn(a2 * di, a3 * di);
    __half2 p2 = __floats2half2_rn(a4 * di, a5 * di);
    __half2 p3 = __floats2half2_rn(a6 * di, a7 * di);
    uint4 o;
    o.x = *(unsigned*)&p0;
    o.y = *(unsigned*)&p1;
    o.z = *(unsigned*)&p2;
    o.w = *(unsigned*)&p3;
    dst[(size_t)node * 16 + l16] = o;
}

// ---------------- fp16 2-MMA split tensor-core GEMM (persistent CTAs) ---------
__device__ __forceinline__ void mma16816h(float* c, const unsigned* a, unsigned b0, unsigned b1) {
    asm volatile(
        "mma.sync.aligned.m16n8k16.row.col.f32.f16.f16.f32 "
        "{%0,%1,%2,%3},{%4,%5,%6,%7},{%8,%9},{%0,%1,%2,%3};"
        : "+f"(c[0]), "+f"(c[1]), "+f"(c[2]), "+f"(c[3])
        : "r"(a[0]), "r"(a[1]), "r"(a[2]), "r"(a[3]), "r"(b0), "r"(b1));
}

// W staged ONCE per CTA; loop over M tiles with stride gridDim.x.
// OUTH: write fp16; PRESCALE: multiply rows by dinv before store (requires OUTH).
template<int KEL, int NTILE, int NVALID, bool RELU, bool OUTH, bool PRESCALE>
__global__ void k_gemm_tc(const __half* __restrict__ Ah, const __half* __restrict__ WtH,
                          const __half* __restrict__ WtL, const float* __restrict__ bias,
                          const float* __restrict__ dinv, void* __restrict__ outv,
                          int nrows, int ldc) {
    constexpr int KSTR  = KEL + 8;
    constexpr int NT    = NTILE / 2;   // warp n-extent
    constexpr int NFRAG = NT / 8;
    extern __shared__ __half smb[];
    __half* As  = smb;                     // 128 x KSTR
    __half* WsH = As + 128 * KSTR;         // NTILE x KSTR
    __half* WsL = WsH + NTILE * KSTR;      // NTILE x KSTR

    int tid = threadIdx.x;
    int n0 = blockIdx.y * NTILE;

    constexpr int C8 = KEL / 8;   // uint4 chunks per row (8 halfs each)
    // stage Wt slice (rows n0..n0+NTILE-1), ONCE
    {
        const uint4* GH = (const uint4*)(WtH + (size_t)n0 * KEL);
        const uint4* GL = (const uint4*)(WtL + (size_t)n0 * KEL);
#pragma unroll
        for (int it = 0; it < NTILE * C8 / 256; it++) {
            int i = tid + 256 * it;
            int r = i / C8, c = i % C8;
            *(uint4*)((char*)WsH + r * (KSTR * 2) + c * 16) = GH[r * C8 + c];
            *(uint4*)((char*)WsL + r * (KSTR * 2) + c * 16) = GL[r * C8 + c];
        }
    }

    int lane = tid & 31, wid = tid >> 5;
    int wm = (wid & 3) * 32;
    int wn = (wid >> 2) * NT;
    int g = lane >> 2, t = lane & 3;

    // hoist bias (and column validity) out of the M loop
    float bv[NFRAG][2];
    bool  cokv[NFRAG];
#pragma unroll
    for (int nt = 0; nt < NFRAG; nt++) {
        int cg = n0 + wn + nt * 8 + 2 * t;
        cokv[nt] = cg < NVALID;
        bv[nt][0] = cokv[nt] ? bias[cg] : 0.f;
        bv[nt][1] = cokv[nt] ? bias[cg + 1] : 0.f;
    }

    int tiles = (nrows + 127) >> 7;
    for (int mb = blockIdx.x; mb < tiles; mb += gridDim.x) {
        int m0 = mb << 7;

        // stage A tile: raw fp16 copy, 16B chunks
        {
            const uint4* GA = (const uint4*)Ah;
#pragma unroll
            for (int it = 0; it < 128 * C8 / 256; it++) {
                int i = tid + 256 * it;
                int r = i / C8, c = i % C8;
                uint4 v = (m0 + r < nrows) ? __ldg(&GA[(size_t)(m0 + r) * C8 + c])
                                           : make_uint4(0u, 0u, 0u, 0u);
                *(uint4*)&As[r * KSTR + c * 8] = v;
            }
        }
        __syncthreads();

        float acc[2][NFRAG][4];
#pragma unroll
        for (int mt = 0; mt < 2; mt++)
#pragma unroll
            for (int nt = 0; nt < NFRAG; nt++)
#pragma unroll
                for (int q = 0; q < 4; q++) acc[mt][nt][q] = 0.f;

#pragma unroll
        for (int ks = 0; ks < KEL / 16; ks++) {
            int k0 = ks * 16;
            unsigned aF[2][4];
#pragma unroll
            for (int mt = 0; mt < 2; mt++) {
                int r = wm + mt * 16;
                aF[mt][0] = *(const unsigned*)&As[(r + g) * KSTR + k0 + 2 * t];
                aF[mt][1] = *(const unsigned*)&As[(r + g + 8) * KSTR + k0 + 2 * t];
                aF[mt][2] = *(const unsigned*)&As[(r + g) * KSTR + k0 + 8 + 2 * t];
                aF[mt][3] = *(const unsigned*)&As[(r + g + 8) * KSTR + k0 + 8 + 2 * t];
            }
#pragma unroll
            for (int nt = 0; nt < NFRAG; nt++) {
                int nn = wn + nt * 8 + g;
                unsigned bH0 = *(const unsigned*)&WsH[nn * KSTR + k0 + 2 * t];
                unsigned bH1 = *(const unsigned*)&WsH[nn * KSTR + k0 + 8 + 2 * t];
                unsigned bL0 = *(const unsigned*)&WsL[nn * KSTR + k0 + 2 * t];
                unsigned bL1 = *(const unsigned*)&WsL[nn * KSTR + k0 + 8 + 2 * t];
#pragma unroll
                for (int mt = 0; mt < 2; mt++) {
                    mma16816h(acc[mt][nt], aF[mt], bH0, bH1);
                    mma16816h(acc[mt][nt], aF[mt], bL0, bL1);
                }
            }
        }

        // epilogue
#pragma unroll
        for (int nt = 0; nt < NFRAG; nt++) {
            int cg = n0 + wn + nt * 8 + 2 * t;
            bool cok = cokv[nt];
            float bv0 = bv[nt][0], bv1 = bv[nt][1];
#pragma unroll
            for (int mt = 0; mt < 2; mt++) {
                int r0 = m0 + wm + mt * 16 + g;
                float v0 = acc[mt][nt][0] + bv0, v1 = acc[mt][nt][1] + bv1;
                float v2 = acc[mt][nt][2] + bv0, v3 = acc[mt][nt][3] + bv1;
                if (RELU) {
                    v0 = fmaxf(v0, 0.f); v1 = fmaxf(v1, 0.f);
                    v2 = fmaxf(v2, 0.f); v3 = fmaxf(v3, 0.f);
                }
                if (OUTH) {
                    float d0 = 1.f, d1 = 1.f;
                    if (PRESCALE) {
                        d0 = (r0 < nrows) ? __ldg(&dinv[r0]) : 0.f;
                        d1 = (r0 + 8 < nrows) ? __ldg(&dinv[r0 + 8]) : 0.f;
                    }
                    __half* oh = (__half*)outv;
                    if (cok && r0 < nrows)
                        *(__half2*)&oh[(size_t)r0 * ldc + cg] = __floats2half2_rn(v0 * d0, v1 * d0);
                    if (cok && r0 + 8 < nrows)
                        *(__half2*)&oh[(size_t)(r0 + 8) * ldc + cg] = __floats2half2_rn(v2 * d1, v3 * d1);
                } else {
                    float* of = (float*)outv;
                    if (cok && r0 < nrows) {
                        of[(size_t)r0 * ldc + cg]     = v0;
                        of[(size_t)r0 * ldc + cg + 1] = v1;
                    }
                    if (cok && r0 + 8 < nrows) {
                        of[(size_t)(r0 + 8) * ldc + cg]     = v2;
                        of[(size_t)(r0 + 8) * ldc + cg + 1] = v3;
                    }
                }
            }
        }
        __syncthreads();   // protect As before next iteration restages
    }
}

#define SMEM_TC  (3 * 128 * 136 * 2)               // 104448 (KEL=128, NTILE=128)
#define SMEM_M2  ((128 + 2 * 64) * 264 * 2)        // 135168 (KEL=256, NTILE=64)

extern "C" void kernel_launch(void* const* d_in, const int* in_sizes, int n_in,
                              void* d_out, int out_size) {
    const float* x   = (const float*)d_in[0];
    const int*   ei  = (const int*)  d_in[1];
    const float* W0  = (const float*)d_in[2];
    const float* b0  = (const float*)d_in[3];
    const float* W1  = (const float*)d_in[4];
    const float* b1  = (const float*)d_in[5];
    const float* W2  = (const float*)d_in[6];
    const float* b2  = (const float*)d_in[7];
    const float* Wm1 = (const float*)d_in[8];
    const float* bm1 = (const float*)d_in[9];
    const float* Wm2 = (const float*)d_in[10];
    const float* bm2 = (const float*)d_in[11];
    float* out = (float*)d_out;

    const int n = Nn, e = Ee;

    int *degi, *offs, *col, *part;
    float *dinv;
    __half *xh, *aggH, *hidH, *wtH, *wtL;
    cudaGetSymbolAddress((void**)&degi, g_degi);
    cudaGetSymbolAddress((void**)&offs, g_offs);
    cudaGetSymbolAddress((void**)&col,  g_col);
    cudaGetSymbolAddress((void**)&part, g_part);
    cudaGetSymbolAddress((void**)&dinv, g_dinv);
    cudaGetSymbolAddress((void**)&xh,   g_xh);
    cudaGetSymbolAddress((void**)&aggH, g_aggH);
    cudaGetSymbolAddress((void**)&hidH, g_hidH);
    cudaGetSymbolAddress((void**)&wtH,  g_wtH);
    cudaGetSymbolAddress((void**)&wtL,  g_wtL);

    cudaFuncSetAttribute(k_gemm_tc<128, 128, 128, true, true, true>,
                         cudaFuncAttributeMaxDynamicSharedMemorySize, SMEM_TC);
    cudaFuncSetAttribute(k_gemm_tc<128, 128, 128, true, true, false>,
                         cudaFuncAttributeMaxDynamicSharedMemorySize, SMEM_TC);
    cudaFuncSetAttribute(k_gemm_tc<128, 128, 256, true, true, false>,
                         cudaFuncAttributeMaxDynamicSharedMemorySize, SMEM_TC);
    cudaFuncSetAttribute(k_gemm_tc<256, 64, 40, false, false, false>,
                         cudaFuncAttributeMaxDynamicSharedMemorySize, SMEM_M2);

    const int TB = 256;
    dim3 gN((n + TB - 1) / TB);
    dim3 gE((e + TB - 1) / TB);
    dim3 gNW(((size_t)n * 16 + TB - 1) / TB);   // 2 nodes per warp
    dim3 gF2H(((size_t)n * 32 + TB - 1) / TB);
    dim3 gP(296, 1);     // persistent: 2 CTAs/SM (104.4 KB smem)
    dim3 gP2(148, 2);    // MLP1: 2 CTAs/SM, one per N half
    dim3 gP1(148, 1);    // MLP2: 1 CTA/SM (135 KB smem)

    // ---- CSR build + normalization (5 launches) ----
    k_zero <<<gN, TB>>>(degi, n);
    k_count<<<gE, TB>>>(ei, degi, e);
    k_scanA<<<NB, 1024>>>(degi, part, dinv);
    k_scanC<<<NB, 1024>>>(degi, part, offs);
    k_fill <<<gE, TB>>>(ei, offs, degi, col, e);

    // ---- fused weight conversion (1 launch) ----
    k_wconv_all<<<(WTOT + 255) / 256, 256>>>(W0, W1, W2, Wm1, Wm2, wtH, wtL);

    // ---- x -> prescaled fp16 ----
    k_f2h<<<gF2H, TB>>>((const float4*)x, dinv, (uint2*)xh, n * 32);

    // ---- layer 0: gather -> fp16 agg, GEMM -> prescaled fp16 h1 (in xh) ----
    k_gather_h<<<gNW, TB>>>(offs, col, dinv, (const uint4*)xh, (uint4*)aggH);
    k_gemm_tc<128, 128, 128, true, true, true><<<gP, TB, SMEM_TC>>>(
        aggH, wtH + WT0, wtL + WT0, b0, dinv, xh, n, 128);

    // ---- layer 1 ----
    k_gather_h<<<gNW, TB>>>(offs, col, dinv, (const uint4*)xh, (uint4*)aggH);
    k_gemm_tc<128, 128, 128, true, true, true><<<gP, TB, SMEM_TC>>>(
        aggH, wtH + WT1, wtL + WT1, b1, dinv, xh, n, 128);

    // ---- layer 2: gather, GEMM -> plain fp16 h3 (in xh) ----
    k_gather_h<<<gNW, TB>>>(offs, col, dinv, (const uint4*)xh, (uint4*)aggH);
    k_gemm_tc<128, 128, 128, true, true, false><<<gP, TB, SMEM_TC>>>(
        aggH, wtH + WT2, wtL + WT2, b2, dinv, xh, n, 128);

    // ---- MLP: h3(fp16) -> hid(fp16) -> out(fp32) ----
    k_gemm_tc<128, 128, 256, true, true, false><<<gP2, TB, SMEM_TC>>>(
        xh, wtH + WTM1, wtL + WTM1, bm1, dinv, hidH, n, 256);
    k_gemm_tc<256, 64, 40, false, false, false><<<gP1, TB, SMEM_M2>>>(
        hidH, wtH + WTM2, wtL + WTM2, bm2, dinv, out, n, 40);
}

// round 16
// speedup vs baseline: 1.0743x; 1.0613x over previous
#include <cuda_runtime.h>
#include <cuda_fp16.h>

#define Nn 100000
#define Ee 1600000
#define Dd 128
#define Hh 256
#define Ll 40
#define NB 98   // ceil(Nn / 1024)

// ---------------- scratch ------------------------------------------------------
__device__ int   g_degi[Nn];
__device__ int   g_offs[Nn + 1];
__device__ int   g_col[Ee];
__device__ int   g_part[NB];
__device__ float g_dinv[Nn];
__device__ __half g_xh[(size_t)Nn * Dd];      // prescaled fp16 features / h3
__device__ __half g_aggH[(size_t)Nn * Dd];    // fp16 gather output
__device__ __half g_hidH[(size_t)Nn * Hh];    // fp16 MLP hidden
// transposed fp16 hi/lo weights [N][K], packed:
//   W0,W1,W2: 128x128 ; Wm1: 256x128 ; Wm2: 64(pad from 40)x256
#define WT0 0
#define WT1 16384
#define WT2 32768
#define WTM1 49152
#define WTM2 81920
#define WTOT 98304
__device__ __half g_wtH[WTOT];
__device__ __half g_wtL[WTOT];

// ---------------- CSR build ----------------------------------------------------
__global__ void k_zero(int* __restrict__ a, int n) {
    int i = blockIdx.x * blockDim.x + threadIdx.x;
    if (i < n) a[i] = 0;
}

__global__ void k_count(const int* __restrict__ ei, int* __restrict__ degi, int e) {
    int i = blockIdx.x * blockDim.x + threadIdx.x;
    if (i < e) atomicAdd(&degi[ei[i]], 1);
}

// block partial sums + dinv (fused)
__global__ void k_scanA(const int* __restrict__ degi, int* __restrict__ part,
                        float* __restrict__ dinv) {
    __shared__ int s[1024];
    int i = blockIdx.x * 1024 + threadIdx.x;
    int v = (i < Nn) ? degi[i] : 0;
    if (i < Nn) dinv[i] = rsqrtf((float)v + 1.0f);
    s[threadIdx.x] = v;
    __syncthreads();
    for (int d = 512; d > 0; d >>= 1) {
        if (threadIdx.x < d) s[threadIdx.x] += s[threadIdx.x + d];
        __syncthreads();
    }
    if (threadIdx.x == 0) part[blockIdx.x] = s[0];
}

// per-block exclusive scan; base computed in-block from partials (fused scanB)
__global__ void k_scanC(const int* __restrict__ degi, const int* __restrict__ part,
                        int* __restrict__ offs) {
    __shared__ int sp[128];
    __shared__ int s[1024];
    int t = threadIdx.x;
    if (t < 128) sp[t] = (t < NB) ? part[t] : 0;
    __syncthreads();
    for (int d = 1; d < 128; d <<= 1) {
        int u = 0;
        if (t < 128 && t >= d) u = sp[t - d];
        __syncthreads();
        if (t < 128) sp[t] += u;
        __syncthreads();
    }
    int base = (blockIdx.x == 0) ? 0 : sp[blockIdx.x - 1];
    int i = blockIdx.x * 1024 + t;
    int v = (i < Nn) ? degi[i] : 0;
    s[t] = v;
    __syncthreads();
    for (int d = 1; d < 1024; d <<= 1) {
        int u = (t >= d) ? s[t - d] : 0;
        __syncthreads();
        s[t] += u;
        __syncthreads();
    }
    int exc = s[t] - v + base;
    if (i < Nn) {
        offs[i] = exc;
        if (i == Nn - 1) offs[Nn] = exc + v;
    }
}

__global__ void k_fill(const int* __restrict__ ei, const int* __restrict__ offs,
                       int* __restrict__ degi, int* __restrict__ col, int e) {
    int i = blockIdx.x * blockDim.x + threadIdx.x;
    if (i < e) {
        int r = ei[i];
        int c = ei[e + i];
        int pos = offs[r] + atomicSub(&degi[r], 1) - 1;
        col[pos] = c;
    }
}

// ---------------- fused weight conversion: all 5 weights -> fp16 hi/lo --------
__global__ void k_wconv_all(const float* __restrict__ W0, const float* __restrict__ W1,
                            const float* __restrict__ W2, const float* __restrict__ Wm1,
                            const float* __restrict__ Wm2,
                            __half* __restrict__ H, __half* __restrict__ L) {
    int i = blockIdx.x * blockDim.x + threadIdx.x;
    if (i >= WTOT) return;
    float w;
    if (i < WTM1) {                       // W0/W1/W2: dest [n][k], K=128, N=128
        const float* W = (i < WT1) ? W0 : (i < WT2) ? W1 : W2;
        int j = i & 16383;
        int n = j >> 7, k = j & 127;
        w = W[k * 128 + n];
    } else if (i < WTM2) {                // Wm1: dest [n][k], n<256, K=128
        int j = i - WTM1;
        int n = j >> 7, k = j & 127;
        w = Wm1[k * 256 + n];
    } else {                              // Wm2: dest [n][k], n<64 (pad 40), K=256
        int j = i - WTM2;
        int n = j >> 8, k = j & 255;
        w = (n < Ll) ? Wm2[k * Ll + n] : 0.f;
    }
    __half h = __float2half_rn(w);
    __half l = __float2half_rn(w - __half2float(h));
    H[i] = h;
    L[i] = l;
}

// ---------------- fp32 -> prescaled fp16: xh = fp16(dinv[row] * x) ------------
__global__ void k_f2h(const float4* __restrict__ x, const float* __restrict__ dinv,
                      uint2* __restrict__ xh, int n4) {
    int t = blockIdx.x * blockDim.x + threadIdx.x;
    if (t < n4) {
        float d = __ldg(&dinv[t >> 5]);
        float4 v = x[t];
        __half2 a = __floats2half2_rn(v.x * d, v.y * d);
        __half2 b = __floats2half2_rn(v.z * d, v.w * d);
        uint2 u;
        u.x = *(unsigned*)&a;
        u.y = *(unsigned*)&b;
        xh[t] = u;
    }
}

// ---------------- aggregation: 2 nodes per warp, 16 lanes each, uint4 ---------
__global__ void k_gather_h(const int* __restrict__ offs, const int* __restrict__ col,
                           const float* __restrict__ dinv, const uint4* __restrict__ src,
                           uint4* __restrict__ dst) {
    int gw   = (int)((blockIdx.x * (size_t)blockDim.x + threadIdx.x) >> 5);
    int lane = threadIdx.x & 31;
    int node = gw * 2 + (lane >> 4);   // two nodes per warp
    int l16  = lane & 15;              // 16 lanes x uint4(8 halfs) = 128 features
    if (node >= Nn) return;

    // self term
    uint4 u = __ldg(&src[(size_t)node * 16 + l16]);
    float2 f0 = __half22float2(*(__half2*)&u.x);
    float2 f1 = __half22float2(*(__half2*)&u.y);
    float2 f2 = __half22float2(*(__half2*)&u.z);
    float2 f3 = __half22float2(*(__half2*)&u.w);
    float a0 = f0.x, a1 = f0.y, a2 = f1.x, a3 = f1.y;
    float a4 = f2.x, a5 = f2.y, a6 = f3.x, a7 = f3.y;

    int beg = __ldg(&offs[node]), end = __ldg(&offs[node + 1]);
    int c = (beg < end) ? __ldg(&col[beg]) : 0;
    for (int j = beg; j < end; j++) {
        int cn = (j + 1 < end) ? __ldg(&col[j + 1]) : 0;   // prefetch next index
        uint4 v = __ldg(&src[(size_t)c * 16 + l16]);
        float2 g0 = __half22float2(*(__half2*)&v.x);
        float2 g1 = __half22float2(*(__half2*)&v.y);
        float2 g2 = __half22float2(*(__half2*)&v.z);
        float2 g3 = __half22float2(*(__half2*)&v.w);
        a0 += g0.x; a1 += g0.y; a2 += g1.x; a3 += g1.y;
        a4 += g2.x; a5 += g2.y; a6 += g3.x; a7 += g3.y;
        c = cn;
    }
    float di = __ldg(&dinv[node]);
    __half2 p0 = __floats2half2_rn(a0 * di, a1 * di);
    __half2 p1 = __floats2half2_rn(a2 * di, a3 * di);
    __half2 p2 = __floats2half2_rn(a4 * di, a5 * di);
    __half2 p3 = __floats2half2_rn(a6 * di, a7 * di);
    uint4 o;
    o.x = *(unsigned*)&p0;
    o.y = *(unsigned*)&p1;
    o.z = *(unsigned*)&p2;
    o.w = *(unsigned*)&p3;
    dst[(size_t)node * 16 + l16] = o;
}

// ---------------- fp16 2-MMA split tensor-core GEMM (persistent + ldmatrix) ---
__device__ __forceinline__ void mma16816h(float* c, const unsigned* a, unsigned b0, unsigned b1) {
    asm volatile(
        "mma.sync.aligned.m16n8k16.row.col.f32.f16.f16.f32 "
        "{%0,%1,%2,%3},{%4,%5,%6,%7},{%8,%9},{%0,%1,%2,%3};"
        : "+f"(c[0]), "+f"(c[1]), "+f"(c[2]), "+f"(c[3])
        : "r"(a[0]), "r"(a[1]), "r"(a[2]), "r"(a[3]), "r"(b0), "r"(b1));
}

__device__ __forceinline__ void ldsm4(unsigned addr, unsigned& r0, unsigned& r1,
                                      unsigned& r2, unsigned& r3) {
    asm volatile("ldmatrix.sync.aligned.m8n8.x4.shared.b16 {%0,%1,%2,%3}, [%4];"
                 : "=r"(r0), "=r"(r1), "=r"(r2), "=r"(r3) : "r"(addr));
}

// W staged ONCE per CTA; loop over M tiles with stride gridDim.x.
// OUTH: write fp16; PRESCALE: multiply rows by dinv before store (requires OUTH).
template<int KEL, int NTILE, int NVALID, bool RELU, bool OUTH, bool PRESCALE>
__global__ void k_gemm_tc(const __half* __restrict__ Ah, const __half* __restrict__ WtH,
                          const __half* __restrict__ WtL, const float* __restrict__ bias,
                          const float* __restrict__ dinv, void* __restrict__ outv,
                          int nrows, int ldc) {
    constexpr int KSTR  = KEL + 8;
    constexpr int NT    = NTILE / 2;   // warp n-extent
    constexpr int NFRAG = NT / 8;
    constexpr int NPAIR = NFRAG / 2;
    extern __shared__ __half smb[];
    __half* As  = smb;                     // 128 x KSTR
    __half* WsH = As + 128 * KSTR;         // NTILE x KSTR
    __half* WsL = WsH + NTILE * KSTR;      // NTILE x KSTR

    int tid = threadIdx.x;
    int n0 = blockIdx.y * NTILE;

    constexpr int C8 = KEL / 8;   // uint4 chunks per row (8 halfs each)
    // stage Wt slice (rows n0..n0+NTILE-1), ONCE
    {
        const uint4* GH = (const uint4*)(WtH + (size_t)n0 * KEL);
        const uint4* GL = (const uint4*)(WtL + (size_t)n0 * KEL);
#pragma unroll
        for (int it = 0; it < NTILE * C8 / 256; it++) {
            int i = tid + 256 * it;
            int r = i / C8, c = i % C8;
            *(uint4*)((char*)WsH + r * (KSTR * 2) + c * 16) = GH[r * C8 + c];
            *(uint4*)((char*)WsL + r * (KSTR * 2) + c * 16) = GL[r * C8 + c];
        }
    }

    int lane = tid & 31, wid = tid >> 5;
    int wm = (wid & 3) * 32;
    int wn = (wid >> 2) * NT;
    int g = lane >> 2, t = lane & 3;

    // ldmatrix base addresses (R4-validated layout)
    unsigned aOff = (unsigned)__cvta_generic_to_shared(As) +
                    (((wm + (lane & 15)) * KSTR + (lane >> 4) * 8) << 1);
    unsigned bOffH = (unsigned)__cvta_generic_to_shared(WsH) +
                     (((wn + (lane & 7) + ((lane >> 4) & 1) * 8) * KSTR +
                       ((lane >> 3) & 1) * 8) << 1);
    unsigned bOffL = bOffH + NTILE * KSTR * 2;

    // hoist bias (and column validity) out of the M loop
    float bv[NFRAG][2];
    bool  cokv[NFRAG];
#pragma unroll
    for (int nt = 0; nt < NFRAG; nt++) {
        int cg = n0 + wn + nt * 8 + 2 * t;
        cokv[nt] = cg < NVALID;
        bv[nt][0] = cokv[nt] ? bias[cg] : 0.f;
        bv[nt][1] = cokv[nt] ? bias[cg + 1] : 0.f;
    }

    int tiles = (nrows + 127) >> 7;
    for (int mb = blockIdx.x; mb < tiles; mb += gridDim.x) {
        int m0 = mb << 7;

        // stage A tile: raw fp16 copy, 16B chunks
        {
            const uint4* GA = (const uint4*)Ah;
#pragma unroll
            for (int it = 0; it < 128 * C8 / 256; it++) {
                int i = tid + 256 * it;
                int r = i / C8, c = i % C8;
                uint4 v = (m0 + r < nrows) ? __ldg(&GA[(size_t)(m0 + r) * C8 + c])
                                           : make_uint4(0u, 0u, 0u, 0u);
                *(uint4*)&As[r * KSTR + c * 8] = v;
            }
        }
        __syncthreads();

        float acc[2][NFRAG][4];
#pragma unroll
        for (int mt = 0; mt < 2; mt++)
#pragma unroll
            for (int nt = 0; nt < NFRAG; nt++)
#pragma unroll
                for (int q = 0; q < 4; q++) acc[mt][nt][q] = 0.f;

#pragma unroll
        for (int ks = 0; ks < KEL / 16; ks++) {
            unsigned ko = (unsigned)(ks * 32);   // 16 halfs = 32 bytes
            unsigned aF[2][4];
            ldsm4(aOff + ko, aF[0][0], aF[0][1], aF[0][2], aF[0][3]);
            ldsm4(aOff + 16 * KSTR * 2 + ko, aF[1][0], aF[1][1], aF[1][2], aF[1][3]);
#pragma unroll
            for (int p = 0; p < NPAIR; p++) {
                unsigned bH[4], bL[4];
                ldsm4(bOffH + p * 16 * KSTR * 2 + ko, bH[0], bH[1], bH[2], bH[3]);
                ldsm4(bOffL + p * 16 * KSTR * 2 + ko, bL[0], bL[1], bL[2], bL[3]);
#pragma unroll
                for (int mt = 0; mt < 2; mt++) {
                    mma16816h(acc[mt][2 * p],     aF[mt], bH[0], bH[1]);
                    mma16816h(acc[mt][2 * p],     aF[mt], bL[0], bL[1]);
                    mma16816h(acc[mt][2 * p + 1], aF[mt], bH[2], bH[3]);
                    mma16816h(acc[mt][2 * p + 1], aF[mt], bL[2], bL[3]);
                }
            }
        }

        // epilogue
#pragma unroll
        for (int nt = 0; nt < NFRAG; nt++) {
            int cg = n0 + wn + nt * 8 + 2 * t;
            bool cok = cokv[nt];
            float bv0 = bv[nt][0], bv1 = bv[nt][1];
#pragma unroll
            for (int mt = 0; mt < 2; mt++) {
                int r0 = m0 + wm + mt * 16 + g;
                float v0 = acc[mt][nt][0] + bv0, v1 = acc[mt][nt][1] + bv1;
                float v2 = acc[mt][nt][2] + bv0, v3 = acc[mt][nt][3] + bv1;
                if (RELU) {
                    v0 = fmaxf(v0, 0.f); v1 = fmaxf(v1, 0.f);
                    v2 = fmaxf(v2, 0.f); v3 = fmaxf(v3, 0.f);
                }
                if (OUTH) {
                    float d0 = 1.f, d1 = 1.f;
                    if (PRESCALE) {
                        d0 = (r0 < nrows) ? __ldg(&dinv[r0]) : 0.f;
                        d1 = (r0 + 8 < nrows) ? __ldg(&dinv[r0 + 8]) : 0.f;
                    }
                    __half* oh = (__half*)outv;
                    if (cok && r0 < nrows)
                        *(__half2*)&oh[(size_t)r0 * ldc + cg] = __floats2half2_rn(v0 * d0, v1 * d0);
                    if (cok && r0 + 8 < nrows)
                        *(__half2*)&oh[(size_t)(r0 + 8) * ldc + cg] = __floats2half2_rn(v2 * d1, v3 * d1);
                } else {
                    float* of = (float*)outv;
                    if (cok && r0 < nrows) {
                        of[(size_t)r0 * ldc + cg]     = v0;
                        of[(size_t)r0 * ldc + cg + 1] = v1;
                    }
                    if (cok && r0 + 8 < nrows) {
                        of[(size_t)(r0 + 8) * ldc + cg]     = v2;
                        of[(size_t)(r0 + 8) * ldc + cg + 1] = v3;
                    }
                }
            }
        }
        __syncthreads();   // protect As before next iteration restages
    }
}

#define SMEM_TC  (3 * 128 * 136 * 2)               // 104448 (KEL=128, NTILE=128)
#define SMEM_M2  ((128 + 2 * 64) * 264 * 2)        // 135168 (KEL=256, NTILE=64)

extern "C" void kernel_launch(void* const* d_in, const int* in_sizes, int n_in,
                              void* d_out, int out_size) {
    const float* x   = (const float*)d_in[0];
    const int*   ei  = (const int*)  d_in[1];
    const float* W0  = (const float*)d_in[2];
    const float* b0  = (const float*)d_in[3];
    const float* W1  = (const float*)d_in[4];
    const float* b1  = (const float*)d_in[5];
    const float* W2  = (const float*)d_in[6];
    const float* b2  = (const float*)d_in[7];
    const float* Wm1 = (const float*)d_in[8];
    const float* bm1 = (const float*)d_in[9];
    const float* Wm2 = (const float*)d_in[10];
    const float* bm2 = (const float*)d_in[11];
    float* out = (float*)d_out;

    const int n = Nn, e = Ee;

    int *degi, *offs, *col, *part;
    float *dinv;
    __half *xh, *aggH, *hidH, *wtH, *wtL;
    cudaGetSymbolAddress((void**)&degi, g_degi);
    cudaGetSymbolAddress((void**)&offs, g_offs);
    cudaGetSymbolAddress((void**)&col,  g_col);
    cudaGetSymbolAddress((void**)&part, g_part);
    cudaGetSymbolAddress((void**)&dinv, g_dinv);
    cudaGetSymbolAddress((void**)&xh,   g_xh);
    cudaGetSymbolAddress((void**)&aggH, g_aggH);
    cudaGetSymbolAddress((void**)&hidH, g_hidH);
    cudaGetSymbolAddress((void**)&wtH,  g_wtH);
    cudaGetSymbolAddress((void**)&wtL,  g_wtL);

    cudaFuncSetAttribute(k_gemm_tc<128, 128, 128, true, true, true>,
                         cudaFuncAttributeMaxDynamicSharedMemorySize, SMEM_TC);
    cudaFuncSetAttribute(k_gemm_tc<128, 128, 128, true, true, false>,
                         cudaFuncAttributeMaxDynamicSharedMemorySize, SMEM_TC);
    cudaFuncSetAttribute(k_gemm_tc<128, 128, 256, true, true, false>,
                         cudaFuncAttributeMaxDynamicSharedMemorySize, SMEM_TC);
    cudaFuncSetAttribute(k_gemm_tc<256, 64, 40, false, false, false>,
                         cudaFuncAttributeMaxDynamicSharedMemorySize, SMEM_M2);

    const int TB = 256;
    dim3 gN((n + TB - 1) / TB);
    dim3 gE((e + TB - 1) / TB);
    dim3 gNW(((size_t)n * 16 + TB - 1) / TB);   // 2 nodes per warp
    dim3 gF2H(((size_t)n * 32 + TB - 1) / TB);
    dim3 gP(296, 1);     // persistent: 2 CTAs/SM (104.4 KB smem)
    dim3 gP2(148, 2);    // MLP1: 2 CTAs/SM, one per N half
    dim3 gP1(148, 1);    // MLP2: 1 CTA/SM (135 KB smem)

    // ---- CSR build + normalization (5 launches) ----
    k_zero <<<gN, TB>>>(degi, n);
    k_count<<<gE, TB>>>(ei, degi, e);
    k_scanA<<<NB, 1024>>>(degi, part, dinv);
    k_scanC<<<NB, 1024>>>(degi, part, offs);
    k_fill <<<gE, TB>>>(ei, offs, degi, col, e);

    // ---- fused weight conversion (1 launch) ----
    k_wconv_all<<<(WTOT + 255) / 256, 256>>>(W0, W1, W2, Wm1, Wm2, wtH, wtL);

    // ---- x -> prescaled fp16 ----
    k_f2h<<<gF2H, TB>>>((const float4*)x, dinv, (uint2*)xh, n * 32);

    // ---- layer 0: gather -> fp16 agg, GEMM -> prescaled fp16 h1 (in xh) ----
    k_gather_h<<<gNW, TB>>>(offs, col, dinv, (const uint4*)xh, (uint4*)aggH);
    k_gemm_tc<128, 128, 128, true, true, true><<<gP, TB, SMEM_TC>>>(
        aggH, wtH + WT0, wtL + WT0, b0, dinv, xh, n, 128);

    // ---- layer 1 ----
    k_gather_h<<<gNW, TB>>>(offs, col, dinv, (const uint4*)xh, (uint4*)aggH);
    k_gemm_tc<128, 128, 128, true, true, true><<<gP, TB, SMEM_TC>>>(
        aggH, wtH + WT1, wtL + WT1, b1, dinv, xh, n, 128);

    // ---- layer 2: gather, GEMM -> plain fp16 h3 (in xh) ----
    k_gather_h<<<gNW, TB>>>(offs, col, dinv, (const uint4*)xh, (uint4*)aggH);
    k_gemm_tc<128, 128, 128, true, true, false><<<gP, TB, SMEM_TC>>>(
        aggH, wtH + WT2, wtL + WT2, b2, dinv, xh, n, 128);

    // ---- MLP: h3(fp16) -> hid(fp16) -> out(fp32) ----
    k_gemm_tc<128, 128, 256, true, true, false><<<gP2, TB, SMEM_TC>>>(
        xh, wtH + WTM1, wtL + WTM1, bm1, dinv, hidH, n, 256);
    k_gemm_tc<256, 64, 40, false, false, false><<<gP1, TB, SMEM_M2>>>(
        hidH, wtH + WTM2, wtL + WTM2, bm2, dinv, out, n, 40);
}